// round 13
// baseline (speedup 1.0000x reference)
#include <cuda_runtime.h>

#define BB 512      // batch rows = threads per block
#define NW 16       // warps per block
#define LL 100      // labels
#define DLEN 100000
#define GAMMA 0.9f
#define SUFP 36     // suffix-table stride (33 entries padded)

__device__ float g_per_label[LL];
__device__ unsigned int g_cnt = 0;

__global__ __launch_bounds__(BB, 1) void map_loss_fused_kernel(
    const float* __restrict__ y_pred,   // (B, L)
    const float* __restrict__ y_true,   // (B, L)
    const int*   __restrict__ index,    // (B,)
    const float* __restrict__ u_all,    // (L, DLEN)
    const float* __restrict__ u_pos,    // (L, DLEN)
    float* __restrict__ out)
{
    __shared__ float  s_key[BB];            // 16 sorted 32-chunks
    __shared__ __align__(16) float4 s_suf4[NW * SUFP];  // (sufV, sufVV, sufFV, sufFVV)
    __shared__ float  s_suff[NW * SUFP];    // suffix positive-count
    __shared__ float  s_fpp[BB];            // compacted positive fp (slot -> fp)
    __shared__ float  s_Sa[BB];             // per-slot S_all
    __shared__ float  s_Sp[BB];             // per-slot S_pos
    __shared__ int    s_wcnt[NW];
    __shared__ float  s_wsum[NW];

    const int l    = blockIdx.x;
    const int t    = threadIdx.x;
    const int warp = t >> 5;
    const int lane = t & 31;

    // ---- issue ALL independent global loads immediately (hidden under the
    // sort/scan phase; R9/R11/R12-verified best front config) ----
    const int   idx  = index[t];
    const float fp_i = y_pred[t * LL + l];
    const float yt   = y_true[t * LL + l];
    const float ua_v = u_all[(long long)l * DLEN + idx];   // stay in regs
    const float up_v = u_pos[(long long)l * DLEN + idx];

    const bool pos_i = (yt == 1.0f);

    const unsigned m = __ballot_sync(0xffffffffu, pos_i);
    if (lane == 0) s_wcnt[warp] = __popc(m);
    __syncthreads();                                            // bar1

    // ---- prefix over warp counts (block-uniform n_pos, per-thread slot) ----
    int base = 0, total = 0;
#pragma unroll
    for (int w = 0; w < NW; w++) {
        int cc = s_wcnt[w];
        if (w < warp) base += cc;
        total += cc;
    }
    const int n_pos = total;                 // >= 1 (row 0 all-positive)
    int my_slot = -1;
    if (pos_i) {
        my_slot = base + __popc(m & ((1u << lane) - 1u));
        s_fpp[my_slot] = fp_i;
    }

    // ---- per-warp bitonic sort of (v, f) in registers: 15 shfl stages ----
    float v = fp_i;
    float f = pos_i ? 1.0f : 0.0f;
#pragma unroll
    for (int k = 2; k <= 32; k <<= 1) {
#pragma unroll
        for (int j = k >> 1; j >= 1; j >>= 1) {
            const float ov = __shfl_xor_sync(0xffffffffu, v, j);
            const float of = __shfl_xor_sync(0xffffffffu, f, j);
            const bool left    = (lane & j) == 0;
            const bool asc     = (lane & k) == 0;
            const bool keepmin = (left == asc);
            const bool take    = keepmin ? (ov < v) : (ov > v);  // ties: no swap
            if (take) { v = ov; f = of; }
        }
    }

    // ---- warp suffix scans (inclusive, Hillis-Steele via shfl_down) ----
    float sv = v, svv = v * v, sf = f, sfv = f * v, sfvv = f * v * v;
#pragma unroll
    for (int off = 1; off < 32; off <<= 1) {
        const float o1 = __shfl_down_sync(0xffffffffu, sv,   off);
        const float o2 = __shfl_down_sync(0xffffffffu, svv,  off);
        const float o3 = __shfl_down_sync(0xffffffffu, sf,   off);
        const float o4 = __shfl_down_sync(0xffffffffu, sfv,  off);
        const float o5 = __shfl_down_sync(0xffffffffu, sfvv, off);
        if (lane + off < 32) { sv += o1; svv += o2; sf += o3; sfv += o4; sfvv += o5; }
    }

    // ---- publish sorted chunk + suffix tables ----
    s_key[warp * 32 + lane] = v;
    const int sb = warp * SUFP;
    s_suf4[sb + lane] = make_float4(sv, svv, sfv, sfvv);
    s_suff[sb + lane] = sf;
    if (lane == 0) {                       // sentinel: empty suffix
        s_suf4[sb + 32] = make_float4(0.f, 0.f, 0.f, 0.f);
        s_suff[sb + 32] = 0.f;
    }
    __syncthreads();                                            // bar2

    // ---- queries: one thread per positive slot (warp-uniform gating) ----
    const int n_q_wrp = (n_pos + 31) >> 5;
    if (warp < n_q_wrp) {
        const bool  act = t < n_pos;
        const float fps = act ? s_fpp[t] : 0.0f;
        const float thr = fps - 1.0f;
        const float c   = -thr;            // == 1 - fps

        float cntAll = 0.f, Sv = 0.f, Svv = 0.f, Fc = 0.f, Fv = 0.f, Fvv = 0.f;
#pragma unroll 4
        for (int w = 0; w < NW; w++) {
            const float* kb = s_key + w * 32;
            // branchless count of elements <= thr in sorted 32-chunk (6 steps)
            int p = 0;
            p += (kb[p + 15] <= thr) ? 16 : 0;
            p += (kb[p + 7]  <= thr) ? 8  : 0;
            p += (kb[p + 3]  <= thr) ? 4  : 0;
            p += (kb[p + 1]  <= thr) ? 2  : 0;
            p += (kb[p]      <= thr) ? 1  : 0;
            p += (kb[p < 31 ? p : 31] <= thr && p < 32) ? 1 : 0;  // final step, p in [0,32]

            cntAll += (float)(32 - p);
            const float4 s4 = s_suf4[w * SUFP + p];
            Sv  += s4.x;  Svv += s4.y;
            Fv  += s4.z;  Fvv += s4.w;
            Fc  += s_suff[w * SUFP + p];
        }
        // S = cnt*c^2 + 2c*Sum(v) + Sum(v^2) over elements v > thr
        const float S_all = fmaf(cntAll * c, c, fmaf(2.0f * c, Sv, Svv));
        const float S_pos = fmaf(Fc * c,     c, fmaf(2.0f * c, Fv, Fvv));
        if (act) { s_Sa[t] = S_all; s_Sp[t] = S_pos; }
    }
    __syncthreads();                                            // bar3

    // ---- each POSITIVE row thread computes its own contribution ----
    float contrib = 0.0f;
    if (pos_i) {
        const float Sa = s_Sa[my_slot];
        const float Sp = s_Sp[my_slot];
        const float ua_new = (1.0f - GAMMA) * ua_v + GAMMA * (Sa * (1.0f / (float)BB));
        const float up_new = (1.0f - GAMMA) * up_v + GAMMA * (Sp * (1.0f / (float)BB));
        contrib = (up_new * Sa - ua_new * Sp) / (ua_new * ua_new);
    }

    // ---- block reduction: warp shuffle + cross-warp fold (deterministic) ----
    float r = contrib;
#pragma unroll
    for (int off = 16; off > 0; off >>= 1)
        r += __shfl_down_sync(0xffffffffu, r, off);
    if (lane == 0) s_wsum[warp] = r;
    __syncthreads();                                            // bar4 (last)

    if (warp == 0) {
        float v2 = (lane < NW) ? s_wsum[lane] : 0.0f;
#pragma unroll
        for (int off = 16; off > 0; off >>= 1)
            v2 += __shfl_down_sync(0xffffffffu, v2, off);

        unsigned old = 0;
        if (lane == 0) {
            g_per_label[l] = v2 / ((float)n_pos * (float)BB);
            // acq_rel RMW: release orders the store above; acquire orders
            // the last block's fold loads. No MEMBAR.GPU pair needed.
            unsigned* cnt_ptr = &g_cnt;
            asm volatile("atom.acq_rel.gpu.global.add.u32 %0, [%1], %2;"
                         : "=r"(old) : "l"(cnt_ptr), "r"(1u) : "memory");
        }
        old = __shfl_sync(0xffffffffu, old, 0);    // warp broadcast

        if (old == LL - 1) {                        // last block: fold 100 values
            volatile float* gp = g_per_label;
            float a = 0.0f;
#pragma unroll
            for (int j = 0; j < 4; j++) {
                const int i2 = lane + j * 32;
                if (i2 < LL) a += gp[i2];
            }
#pragma unroll
            for (int off = 16; off > 0; off >>= 1)
                a += __shfl_down_sync(0xffffffffu, a, off);
            if (lane == 0) {
                out[0] = a / (float)LL;
                g_cnt = 0;                          // reset for next replay
            }
        }
    }
}

extern "C" void kernel_launch(void* const* d_in, const int* in_sizes, int n_in,
                              void* d_out, int out_size) {
    const float* y_pred = (const float*)d_in[0];
    const float* y_true = (const float*)d_in[1];
    const int*   index  = (const int*)d_in[2];
    const float* u_all  = (const float*)d_in[3];
    const float* u_pos  = (const float*)d_in[4];
    float* out = (float*)d_out;

    map_loss_fused_kernel<<<LL, BB>>>(y_pred, y_true, index, u_all, u_pos, out);
}

// round 14
// speedup vs baseline: 1.0363x; 1.0363x over previous
#include <cuda_runtime.h>

#define BB 512      // batch rows = threads per block
#define NW 16       // warps per block
#define LL 100      // labels
#define DLEN 100000
#define GAMMA 0.9f
#define SUFP 36     // suffix-table stride (33 entries padded)

__device__ float g_per_label[LL];
__device__ unsigned int g_cnt = 0;

// Breadth-first (lockstep) binary search + suffix accumulation over C
// consecutive sorted 32-chunks. All loads within a step are independent.
template<int C>
__device__ __forceinline__ void query_chunks(
    const float* __restrict__ s_key,
    const float4* __restrict__ s_suf4,
    const float* __restrict__ s_suff,
    float thr, int wbeg,
    float& cnt, float& Sv, float& Svv, float& Fc, float& Fv, float& Fvv)
{
    int p[C];
#pragma unroll
    for (int j = 0; j < C; j++)
        p[j] = (s_key[(wbeg + j) * 32 + 15] <= thr) ? 16 : 0;
#pragma unroll
    for (int j = 0; j < C; j++)
        p[j] += (s_key[(wbeg + j) * 32 + p[j] + 7] <= thr) ? 8 : 0;
#pragma unroll
    for (int j = 0; j < C; j++)
        p[j] += (s_key[(wbeg + j) * 32 + p[j] + 3] <= thr) ? 4 : 0;
#pragma unroll
    for (int j = 0; j < C; j++)
        p[j] += (s_key[(wbeg + j) * 32 + p[j] + 1] <= thr) ? 2 : 0;
#pragma unroll
    for (int j = 0; j < C; j++)
        p[j] += (s_key[(wbeg + j) * 32 + p[j]] <= thr) ? 1 : 0;
#pragma unroll
    for (int j = 0; j < C; j++)   // final step: p may reach 32 (all <= thr)
        p[j] += (p[j] < 32 && s_key[(wbeg + j) * 32 + (p[j] < 31 ? p[j] : 31)] <= thr) ? 1 : 0;

#pragma unroll
    for (int j = 0; j < C; j++) {
        const int pp = p[j];
        cnt += (float)(32 - pp);
        const float4 s4 = s_suf4[(wbeg + j) * SUFP + pp];
        Sv  += s4.x;  Svv += s4.y;
        Fv  += s4.z;  Fvv += s4.w;
        Fc  += s_suff[(wbeg + j) * SUFP + pp];
    }
}

__global__ __launch_bounds__(BB, 1) void map_loss_fused_kernel(
    const float* __restrict__ y_pred,   // (B, L)
    const float* __restrict__ y_true,   // (B, L)
    const int*   __restrict__ index,    // (B,)
    const float* __restrict__ u_all,    // (L, DLEN)
    const float* __restrict__ u_pos,    // (L, DLEN)
    float* __restrict__ out)
{
    __shared__ float  s_key[BB];            // 16 sorted 32-chunks
    __shared__ __align__(16) float4 s_suf4[NW * SUFP];  // (sufV, sufVV, sufFV, sufFVV)
    __shared__ float  s_suff[NW * SUFP];    // suffix positive-count
    __shared__ float  s_fpp[BB];            // compacted positive fp (slot -> fp)
    __shared__ float  s_Sa[BB];             // per-slot S_all
    __shared__ float  s_Sp[BB];             // per-slot S_pos
    __shared__ int    s_wcnt[NW];
    __shared__ float  s_wsum[NW];

    const int l    = blockIdx.x;
    const int t    = threadIdx.x;
    const int warp = t >> 5;
    const int lane = t & 31;

    // ---- issue ALL independent global loads immediately (hidden under the
    // sort/scan phase) ----
    const int   idx  = index[t];
    const float fp_i = y_pred[t * LL + l];
    const float yt   = y_true[t * LL + l];
    const float ua_v = u_all[(long long)l * DLEN + idx];   // stay in regs
    const float up_v = u_pos[(long long)l * DLEN + idx];

    const bool pos_i = (yt == 1.0f);

    const unsigned m = __ballot_sync(0xffffffffu, pos_i);
    if (lane == 0) s_wcnt[warp] = __popc(m);
    __syncthreads();                                            // bar1

    // ---- prefix over warp counts (block-uniform n_pos, per-thread slot) ----
    int base = 0, total = 0;
#pragma unroll
    for (int w = 0; w < NW; w++) {
        int cc = s_wcnt[w];
        if (w < warp) base += cc;
        total += cc;
    }
    const int n_pos = total;                 // >= 1 (row 0 all-positive)
    int my_slot = -1;
    if (pos_i) {
        my_slot = base + __popc(m & ((1u << lane) - 1u));
        s_fpp[my_slot] = fp_i;
    }

    // ---- per-warp bitonic sort of (v, f) in registers: 15 shfl stages ----
    float v = fp_i;
    float f = pos_i ? 1.0f : 0.0f;
#pragma unroll
    for (int k = 2; k <= 32; k <<= 1) {
#pragma unroll
        for (int j = k >> 1; j >= 1; j >>= 1) {
            const float ov = __shfl_xor_sync(0xffffffffu, v, j);
            const float of = __shfl_xor_sync(0xffffffffu, f, j);
            const bool left    = (lane & j) == 0;
            const bool asc     = (lane & k) == 0;
            const bool keepmin = (left == asc);
            const bool take    = keepmin ? (ov < v) : (ov > v);  // ties: no swap
            if (take) { v = ov; f = of; }
        }
    }

    // ---- warp suffix scans (inclusive, Hillis-Steele via shfl_down) ----
    float sv = v, svv = v * v, sf = f, sfv = f * v, sfvv = f * v * v;
#pragma unroll
    for (int off = 1; off < 32; off <<= 1) {
        const float o1 = __shfl_down_sync(0xffffffffu, sv,   off);
        const float o2 = __shfl_down_sync(0xffffffffu, svv,  off);
        const float o3 = __shfl_down_sync(0xffffffffu, sf,   off);
        const float o4 = __shfl_down_sync(0xffffffffu, sfv,  off);
        const float o5 = __shfl_down_sync(0xffffffffu, sfvv, off);
        if (lane + off < 32) { sv += o1; svv += o2; sf += o3; sfv += o4; sfvv += o5; }
    }

    // ---- publish sorted chunk + suffix tables ----
    s_key[warp * 32 + lane] = v;
    const int sb = warp * SUFP;
    s_suf4[sb + lane] = make_float4(sv, svv, sfv, sfvv);
    s_suff[sb + lane] = sf;
    if (lane == 0) {                       // sentinel: empty suffix
        s_suf4[sb + 32] = make_float4(0.f, 0.f, 0.f, 0.f);
        s_suff[sb + 32] = 0.f;
    }
    __syncthreads();                                            // bar2

    // ---- K-split queries: K threads per positive slot, 16/K chunks each ----
    const int n4 = 4 * n_pos, n2 = 2 * n_pos;
    int n_act_thr, Ksel;
    if (n4 <= BB)      { Ksel = 4; n_act_thr = n4; }
    else if (n2 <= BB) { Ksel = 2; n_act_thr = n2; }
    else               { Ksel = 1; n_act_thr = n_pos; }
    const int n_act_wrp = (n_act_thr + 31) >> 5;

    if (warp < n_act_wrp) {                // warp-uniform; idle warps skip
        const bool act = t < n_act_thr;

        int slot, sub;
        if (Ksel == 4)      { slot = t >> 2; sub = t & 3; }
        else if (Ksel == 2) { slot = t >> 1; sub = t & 1; }
        else                { slot = t;      sub = 0;     }

        const float fps = act ? s_fpp[slot] : 0.0f;
        const float thr = fps - 1.0f;
        const float c   = -thr;            // == 1 - fps

        float cnt = 0.f, Sv = 0.f, Svv = 0.f, Fc = 0.f, Fv = 0.f, Fvv = 0.f;
        if (Ksel == 4) {
            query_chunks<4>(s_key, s_suf4, s_suff, thr, sub * 4, cnt, Sv, Svv, Fc, Fv, Fvv);
        } else if (Ksel == 2) {
            query_chunks<8>(s_key, s_suf4, s_suff, thr, sub * 8, cnt, Sv, Svv, Fc, Fv, Fvv);
        } else {
            query_chunks<16>(s_key, s_suf4, s_suff, thr, 0, cnt, Sv, Svv, Fc, Fv, Fvv);
        }

        // S = cnt*c^2 + 2c*Sum(v) + Sum(v^2) over elements v > thr
        float S_all = fmaf(cnt * c, c, fmaf(2.0f * c, Sv, Svv));
        float S_pos = fmaf(Fc  * c, c, fmaf(2.0f * c, Fv, Fvv));

        // combine K partials (group of K lanes; warp-uniform shuffles)
        if (Ksel >= 2) {
            S_all += __shfl_xor_sync(0xffffffffu, S_all, 1);
            S_pos += __shfl_xor_sync(0xffffffffu, S_pos, 1);
        }
        if (Ksel == 4) {
            S_all += __shfl_xor_sync(0xffffffffu, S_all, 2);
            S_pos += __shfl_xor_sync(0xffffffffu, S_pos, 2);
        }

        if (act && sub == 0) { s_Sa[slot] = S_all; s_Sp[slot] = S_pos; }
    }
    __syncthreads();                                            // bar3

    // ---- each POSITIVE row thread computes its own contribution ----
    float contrib = 0.0f;
    if (pos_i) {
        const float Sa = s_Sa[my_slot];
        const float Sp = s_Sp[my_slot];
        const float ua_new = (1.0f - GAMMA) * ua_v + GAMMA * (Sa * (1.0f / (float)BB));
        const float up_new = (1.0f - GAMMA) * up_v + GAMMA * (Sp * (1.0f / (float)BB));
        contrib = (up_new * Sa - ua_new * Sp) / (ua_new * ua_new);
    }

    // ---- block reduction: warp shuffle + cross-warp fold (deterministic) ----
    float r = contrib;
#pragma unroll
    for (int off = 16; off > 0; off >>= 1)
        r += __shfl_down_sync(0xffffffffu, r, off);
    if (lane == 0) s_wsum[warp] = r;
    __syncthreads();                                            // bar4 (last)

    if (warp == 0) {
        float v2 = (lane < NW) ? s_wsum[lane] : 0.0f;
#pragma unroll
        for (int off = 16; off > 0; off >>= 1)
            v2 += __shfl_down_sync(0xffffffffu, v2, off);

        unsigned old = 0;
        if (lane == 0) {
            g_per_label[l] = v2 / ((float)n_pos * (float)BB);
            unsigned* cnt_ptr = &g_cnt;
            asm volatile("atom.acq_rel.gpu.global.add.u32 %0, [%1], %2;"
                         : "=r"(old) : "l"(cnt_ptr), "r"(1u) : "memory");
        }
        old = __shfl_sync(0xffffffffu, old, 0);    // warp broadcast

        if (old == LL - 1) {                        // last block: fold 100 values
            volatile float* gp = g_per_label;
            float a = 0.0f;
#pragma unroll
            for (int j = 0; j < 4; j++) {
                const int i2 = lane + j * 32;
                if (i2 < LL) a += gp[i2];
            }
#pragma unroll
            for (int off = 16; off > 0; off >>= 1)
                a += __shfl_down_sync(0xffffffffu, a, off);
            if (lane == 0) {
                out[0] = a / (float)LL;
                g_cnt = 0;                          // reset for next replay
            }
        }
    }
}

extern "C" void kernel_launch(void* const* d_in, const int* in_sizes, int n_in,
                              void* d_out, int out_size) {
    const float* y_pred = (const float*)d_in[0];
    const float* y_true = (const float*)d_in[1];
    const int*   index  = (const int*)d_in[2];
    const float* u_all  = (const float*)d_in[3];
    const float* u_pos  = (const float*)d_in[4];
    float* out = (float*)d_out;

    map_loss_fused_kernel<<<LL, BB>>>(y_pred, y_true, index, u_all, u_pos, out);
}

// round 15
// speedup vs baseline: 1.2610x; 1.2169x over previous
#include <cuda_runtime.h>

#define BB 512      // batch rows = threads per block
#define NW 16       // warps per block
#define LL 100      // labels
#define DLEN 100000
#define GAMMA 0.9f

__device__ float g_per_label[LL];
__device__ unsigned int g_cnt = 0;

// Packed f32x2 sweep over the SORTED array: positive prefix [0, np4) feeds
// S_pos; negative suffix [np4, np4+na4) feeds the remainder of S_all.
// Each thread takes the 1/K interleaved slice of both ranges.
template<int K>
__device__ __forceinline__ void compute_sums_sorted(
    const ulonglong2* __restrict__ srt2, int np4, int na4,
    unsigned long long c2, int sub, float& S_all, float& S_pos)
{
    // positive prefix
    unsigned long long p0 = 0ull, p1 = 0ull;
    const int hp = np4 / K;             // np4 multiple of K*2/2 (see padding)
#pragma unroll 4
    for (int jj = 0; jj < hp; jj++) {
        ulonglong2 v = srt2[K * jj + sub];
        asm("{\n\t"
            ".reg .b64 e0, e1;\n\t"
            ".reg .f32 x0, x1, x2, x3;\n\t"
            "add.rn.f32x2 e0, %2, %4;\n\t"
            "add.rn.f32x2 e1, %3, %4;\n\t"
            "mov.b64 {x0, x1}, e0;\n\t"
            "mov.b64 {x2, x3}, e1;\n\t"
            "max.f32 x0, x0, 0f00000000;\n\t"
            "max.f32 x1, x1, 0f00000000;\n\t"
            "max.f32 x2, x2, 0f00000000;\n\t"
            "max.f32 x3, x3, 0f00000000;\n\t"
            "mov.b64 e0, {x0, x1};\n\t"
            "mov.b64 e1, {x2, x3};\n\t"
            "fma.rn.f32x2 %0, e0, e0, %0;\n\t"
            "fma.rn.f32x2 %1, e1, e1, %1;\n\t"
            "}" : "+l"(p0), "+l"(p1) : "l"(v.x), "l"(v.y), "l"(c2));
    }
    float pl0, ph0, pl1, ph1;
    asm("mov.b64 {%0, %1}, %2;" : "=f"(pl0), "=f"(ph0) : "l"(p0));
    asm("mov.b64 {%0, %1}, %2;" : "=f"(pl1), "=f"(ph1) : "l"(p1));
    S_pos = (pl0 + ph0) + (pl1 + ph1);

    // negative suffix
    unsigned long long a0 = 0ull, a1 = 0ull;
    const int ha = na4 / K;
#pragma unroll 4
    for (int jj = 0; jj < ha; jj++) {
        ulonglong2 v = srt2[np4 + K * jj + sub];
        asm("{\n\t"
            ".reg .b64 e0, e1;\n\t"
            ".reg .f32 x0, x1, x2, x3;\n\t"
            "add.rn.f32x2 e0, %2, %4;\n\t"
            "add.rn.f32x2 e1, %3, %4;\n\t"
            "mov.b64 {x0, x1}, e0;\n\t"
            "mov.b64 {x2, x3}, e1;\n\t"
            "max.f32 x0, x0, 0f00000000;\n\t"
            "max.f32 x1, x1, 0f00000000;\n\t"
            "max.f32 x2, x2, 0f00000000;\n\t"
            "max.f32 x3, x3, 0f00000000;\n\t"
            "mov.b64 e0, {x0, x1};\n\t"
            "mov.b64 e1, {x2, x3};\n\t"
            "fma.rn.f32x2 %0, e0, e0, %0;\n\t"
            "fma.rn.f32x2 %1, e1, e1, %1;\n\t"
            "}" : "+l"(a0), "+l"(a1) : "l"(v.x), "l"(v.y), "l"(c2));
    }
    float al0, ah0, al1, ah1;
    asm("mov.b64 {%0, %1}, %2;" : "=f"(al0), "=f"(ah0) : "l"(a0));
    asm("mov.b64 {%0, %1}, %2;" : "=f"(al1), "=f"(ah1) : "l"(a1));
    S_all = S_pos + ((al0 + ah0) + (al1 + ah1));
}

__global__ __launch_bounds__(BB, 1) void map_loss_fused_kernel(
    const float* __restrict__ y_pred,   // (B, L)
    const float* __restrict__ y_true,   // (B, L)
    const int*   __restrict__ index,    // (B,)
    const float* __restrict__ u_all,    // (L, DLEN)
    const float* __restrict__ u_pos,    // (L, DLEN)
    float* __restrict__ out)
{
    // sorted fp: [0,n_pos) positives (padded), then negatives (padded).
    __shared__ __align__(16) float s_srt[BB + 32];
    __shared__ float s_Sa[BB];          // per-slot S_all
    __shared__ float s_Sp[BB];          // per-slot S_pos
    __shared__ int   s_wcnt[NW];
    __shared__ float s_wsum[NW];

    const int l    = blockIdx.x;
    const int t    = threadIdx.x;
    const int warp = t >> 5;
    const int lane = t & 31;

    // ---- issue ALL independent global loads immediately (hidden under
    // compaction + mainloop; verified best front config R9/R11/R12) ----
    const int   idx  = index[t];
    const float fp_i = y_pred[t * LL + l];
    const float yt   = y_true[t * LL + l];
    const float ua_v = u_all[(long long)l * DLEN + idx];   // stay in regs
    const float up_v = u_pos[(long long)l * DLEN + idx];

    const bool pos_i = (yt == 1.0f);
    s_srt[t] = -1e30f;                  // pad entries -> relu = 0
    if (t < 32) s_srt[BB + t] = -1e30f;

    const unsigned m = __ballot_sync(0xffffffffu, pos_i);
    if (lane == 0) s_wcnt[warp] = __popc(m);
    __syncthreads();                                            // bar1

    // ---- prefix over warp counts; deterministic 2-way compaction ----
    int base = 0, total = 0;
#pragma unroll
    for (int w = 0; w < NW; w++) {
        int cc = s_wcnt[w];
        if (w < warp) base += cc;
        total += cc;
    }
    const int n_pos = total;                       // >= 1

    // ---- K selection first (block-uniform) so padding can match K ----
    const int n4 = 4 * n_pos, n2 = 2 * n_pos;
    int n_act_thr, Ksel, pad;
    if (n4 <= BB)      { Ksel = 4; n_act_thr = n4;    pad = 16; }
    else if (n2 <= BB) { Ksel = 2; n_act_thr = n2;    pad = 8;  }
    else               { Ksel = 1; n_act_thr = n_pos; pad = 8;  }

    const int n_pos_pad = (n_pos + pad - 1) & ~(pad - 1);
    const int np4       = n_pos_pad >> 2;          // multiple of K
    const int n_neg     = BB - n_pos;
    const int na4       = ((n_neg + pad - 1) & ~(pad - 1)) >> 2;

    const int lane_pos = __popc(m & ((1u << lane) - 1u));
    int my_slot = -1;
    if (pos_i) {
        my_slot = base + lane_pos;
        s_srt[my_slot] = fp_i;
    } else {
        // negatives-before-me = (32*warp - base) + (lane - lane_pos)
        const int noff = (32 * warp - base) + (lane - lane_pos);
        s_srt[n_pos_pad + noff] = fp_i;
    }
    __syncthreads();                                            // bar2

    const int n_act_wrp = (n_act_thr + 31) >> 5;

    if (warp < n_act_wrp) {             // warp-uniform; idle warps skip
        const bool act = t < n_act_thr;
        const ulonglong2* srt2 = reinterpret_cast<const ulonglong2*>(s_srt);

        int slot, sub;
        float S_all = 0.f, S_pos = 0.f;
        if (Ksel == 4)      { slot = t >> 2; sub = t & 3; }
        else if (Ksel == 2) { slot = t >> 1; sub = t & 1; }
        else                { slot = t;      sub = 0;     }

        const float cs = act ? (1.0f - s_srt[slot]) : -1e30f;
        unsigned long long c2;
        asm("mov.b64 %0, {%1, %1};" : "=l"(c2) : "f"(cs));

        if (Ksel == 4) {
            compute_sums_sorted<4>(srt2, np4, na4, c2, sub, S_all, S_pos);
            S_all += __shfl_xor_sync(0xffffffffu, S_all, 1);
            S_all += __shfl_xor_sync(0xffffffffu, S_all, 2);
            S_pos += __shfl_xor_sync(0xffffffffu, S_pos, 1);
            S_pos += __shfl_xor_sync(0xffffffffu, S_pos, 2);
        } else if (Ksel == 2) {
            compute_sums_sorted<2>(srt2, np4, na4, c2, sub, S_all, S_pos);
            S_all += __shfl_xor_sync(0xffffffffu, S_all, 1);
            S_pos += __shfl_xor_sync(0xffffffffu, S_pos, 1);
        } else {
            compute_sums_sorted<1>(srt2, np4, na4, c2, sub, S_all, S_pos);
        }

        if (act && sub == 0) {          // publish per-slot sums
            s_Sa[slot] = S_all;
            s_Sp[slot] = S_pos;
        }
    }
    __syncthreads();                                            // bar3

    // ---- each POSITIVE row thread computes its own contribution ----
    float contrib = 0.0f;
    if (pos_i) {
        const float Sa = s_Sa[my_slot];
        const float Sp = s_Sp[my_slot];
        const float ua_new = (1.0f - GAMMA) * ua_v + GAMMA * (Sa * (1.0f / (float)BB));
        const float up_new = (1.0f - GAMMA) * up_v + GAMMA * (Sp * (1.0f / (float)BB));
        contrib = (up_new * Sa - ua_new * Sp) / (ua_new * ua_new);
    }

    // ---- block reduction: warp shuffle + cross-warp fold (deterministic) ----
    float v = contrib;
#pragma unroll
    for (int off = 16; off > 0; off >>= 1)
        v += __shfl_down_sync(0xffffffffu, v, off);
    if (lane == 0) s_wsum[warp] = v;
    __syncthreads();                                            // bar4 (last)

    if (warp == 0) {
        float v2 = (lane < NW) ? s_wsum[lane] : 0.0f;
#pragma unroll
        for (int off = 16; off > 0; off >>= 1)
            v2 += __shfl_down_sync(0xffffffffu, v2, off);

        unsigned old = 0;
        if (lane == 0) {
            g_per_label[l] = v2 / ((float)n_pos * (float)BB);
            // acq_rel RMW: release orders the store above; acquire orders
            // the last block's fold loads. No MEMBAR.GPU pair needed.
            unsigned* cnt_ptr = &g_cnt;
            asm volatile("atom.acq_rel.gpu.global.add.u32 %0, [%1], %2;"
                         : "=r"(old) : "l"(cnt_ptr), "r"(1u) : "memory");
        }
        old = __shfl_sync(0xffffffffu, old, 0);    // warp broadcast

        if (old == LL - 1) {                        // last block: fold 100 values
            volatile float* gp = g_per_label;
            float a = 0.0f;
#pragma unroll
            for (int j = 0; j < 4; j++) {
                const int i2 = lane + j * 32;
                if (i2 < LL) a += gp[i2];
            }
#pragma unroll
            for (int off = 16; off > 0; off >>= 1)
                a += __shfl_down_sync(0xffffffffu, a, off);
            if (lane == 0) {
                out[0] = a / (float)LL;
                g_cnt = 0;                          // reset for next replay
            }
        }
    }
}

extern "C" void kernel_launch(void* const* d_in, const int* in_sizes, int n_in,
                              void* d_out, int out_size) {
    const float* y_pred = (const float*)d_in[0];
    const float* y_true = (const float*)d_in[1];
    const int*   index  = (const int*)d_in[2];
    const float* u_all  = (const float*)d_in[3];
    const float* u_pos  = (const float*)d_in[4];
    float* out = (float*)d_out;

    map_loss_fused_kernel<<<LL, BB>>>(y_pred, y_true, index, u_all, u_pos, out);
}